// round 11
// baseline (speedup 1.0000x reference)
#include <cuda_runtime.h>
#include <cuda_bf16.h>

// preds: [16,8,17,128,128] f32 -> N=128 groups, K=17, H=W=128
// gt:    [16,8,10,17,2]    f32 -> N=128, P=10, K=17, (x,y)
// FEAT_STRIDE = 4.0; out: [2] f32 = (within, across)

#define P_PERSONS 10
#define K_KPS     17
#define HMAP      128
#define WMAP      128
#define KP_HALF   9     // keypoints per lane (h=0: k0..8, h=1: k9..16 +1 masked)

// Single packed accumulator:
//   bits[36:64) : sum of per-group within  (fixed-point, scale 2^18)
//   bits[ 8:36) : sum of per-group across  (fixed-point, scale 2^20)
//   bits[ 0: 8) : arrival count (N=128 < 256)
// Fields are non-negative and bounded -> no cross-field carry. Integer adds
// are associative -> bit-deterministic across graph replays. Zero-init at
// module load; the last warp resets it to 0.
__device__ unsigned long long g_acc;

#define QS        262144.0f            // 2^18 (lane-level quantization)
#define QS_INV    3.814697265625e-6f   // 2^-18
#define W_SCALE   262144.0f            // 2^18
#define A_SCALE   1048576.0f           // 2^20
#define W_INV     3.814697265625e-6f   // 2^-18
#define A_INV     9.5367431640625e-7f  // 2^-20

#define GROUPS_PER_CTA 2

__global__ __launch_bounds__(32 * GROUPS_PER_CTA, 8)
void group_loss_fused(const float* __restrict__ preds,
                      const float* __restrict__ gt,
                      float* __restrict__ out,
                      int N)
{
    // One warp per group; GROUPS_PER_CTA warps per CTA, fully independent.
    const int n    = blockIdx.x * GROUPS_PER_CTA + (threadIdx.x >> 5);
    const int lane = threadIdx.x & 31;
    const int p    = lane >> 1;            // person id (lanes 0..19)
    const int h    = lane & 1;             // half: 0 -> k0..8, 1 -> k9..16
    const bool active = (lane < 2 * P_PERSONS);

    float a0 = 0.0f, a1 = 0.0f, a2 = 0.0f;

    if (active) {
        const float2* gp = reinterpret_cast<const float2*>(gt)
                         + (n * P_PERSONS + p) * K_KPS;
        const float* pbase = preds + (size_t)n * K_KPS * (HMAP * WMAP);
        const int k0 = h ? 9 : 0;

        // Wave 1: 9 gt coords in flight at once (one overlapped latency).
        float2 gxy[KP_HALF];
        #pragma unroll
        for (int k = 0; k < KP_HALF; k++) {
            const int kk = min(k0 + k, K_KPS - 1);     // clamp keeps load in-bounds
            gxy[k] = __ldg(gp + kk);
        }

        int   off[KP_HALF];
        float msk[KP_HALF];
        #pragma unroll
        for (int k = 0; k < KP_HALF; k++) {
            const int kk = min(k0 + k, K_KPS - 1);
            // jnp.round == round-half-to-even == rintf (RN mode)
            const int x = (int)rintf(gxy[k].x * 0.25f);
            const int y = (int)rintf(gxy[k].y * 0.25f);
            bool v = (x >= 0) & (x < WMAP) & (y >= 0) & (y < HMAP);
            if (k0 + k > K_KPS - 1) v = false;          // mask the duplicate kp
            const int xc = min(max(x, 0), WMAP - 1);
            const int yc = min(max(y, 0), HMAP - 1);
            off[k] = kk * (HMAP * WMAP) + yc * WMAP + xc;
            msk[k] = v ? 1.0f : 0.0f;
        }

        // Wave 2: 9 gathers in flight at once (second overlapped latency).
        float val[KP_HALF];
        #pragma unroll
        for (int k = 0; k < KP_HALF; k++)
            val[k] = __ldg(pbase + off[k]);

        #pragma unroll
        for (int k = 0; k < KP_HALF; k++) {
            const float vm = val[k] * msk[k];
            a0 += vm;
            a1 += vm * val[k];
            a2 += msk[k];
        }
    }

    // Merge the two half-person partials (both lanes of the pair get sums).
    a0 += __shfl_xor_sync(0xFFFFFFFFu, a0, 1);
    a1 += __shfl_xor_sync(0xFFFFFFFFu, a1, 1);
    a2 += __shfl_xor_sync(0xFFFFFFFFu, a2, 1);

    const float safe = fmaxf(a2, 1.0f);
    const float inv  = __fdividef(1.0f, safe);
    const float e    = a0 * inv;                       // person embed (0 if cnt==0)
    const float pv   = (a2 > 0.0f) ? 1.0f : 0.0f;
    // within = E[v^2] - e^2 (exactly 0 when cnt==0; clamp fp32 cancellation)
    const float within_p = fmaxf(a1 * inv - e * e, 0.0f);

    // Hinge rows; embeds broadcast from even lanes. Lanes >= 20 have pv == 0.
    float hs = 0.0f;
    #pragma unroll
    for (int j = 0; j < P_PERSONS; j++) {
        const float ej  = __shfl_sync(0xFFFFFFFFu, e,  j << 1);
        const float pvj = __shfl_sync(0xFFFFFFFFu, pv, j << 1);
        if (j != p)
            hs += fmaxf(1.0f - fabsf(ej - e), 0.0f) * (pv * pvj);
    }
    const bool rowlane = active && (h == 0);

    // Single-instruction warp reductions on quantized values (deterministic).
    const unsigned wq  = rowlane ? __float2uint_rn(within_p * QS) : 0u;
    const unsigned hq  = rowlane ? __float2uint_rn(hs * QS)       : 0u;
    const unsigned vq  = (rowlane && pv > 0.0f) ? 1u : 0u;
    const unsigned wqt = __reduce_add_sync(0xFFFFFFFFu, wq);
    const unsigned hqt = __reduce_add_sync(0xFFFFFFFFu, hq);
    const unsigned vct = __reduce_add_sync(0xFFFFFFFFu, vq);

    if (lane == 0) {
        const float vcnt   = (float)vct;
        const float ps     = vcnt * vcnt - vcnt;        // off-diagonal valid pairs
        const float part_w = (float)wqt * QS_INV * (1.0f / (float)P_PERSONS);
        const float part_a = (ps > 0.0f)
                           ? __fdividef((float)hqt * QS_INV, ps) : 0.0f;

        const unsigned long long wfx = (unsigned long long)__float2uint_rn(part_w * W_SCALE);
        const unsigned long long afx = (unsigned long long)__float2uint_rn(part_a * A_SCALE);
        const unsigned long long packed = (wfx << 36) | (afx << 8) | 1ULL;

        // Single atomic: accumulates AND detects the last arriver.
        unsigned long long old;
        asm volatile("atom.relaxed.gpu.global.add.u64 %0, [%1], %2;"
                     : "=l"(old) : "l"(&g_acc), "l"(packed) : "memory");

        if ((old & 0xFFULL) == (unsigned long long)(N - 1)) {
            const unsigned long long tot = old + packed;
            // Reset for next graph replay (same-address coherence orders
            // this after every warp's add, all of which precede ours).
            asm volatile("st.relaxed.gpu.global.u64 [%0], %1;"
                         :: "l"(&g_acc), "l"(0ULL) : "memory");
            const float inv_n = 1.0f / (float)N;
            const float wt = (float)(unsigned int)(tot >> 36);
            const float at = (float)(unsigned int)((tot >> 8) & 0xFFFFFFFULL);
            float2 res;
            res.x = wt * W_INV * inv_n;
            res.y = at * A_INV * inv_n;
            *reinterpret_cast<float2*>(out) = res;
        }
    }
}

extern "C" void kernel_launch(void* const* d_in, const int* in_sizes, int n_in,
                              void* d_out, int out_size)
{
    const float* preds = (const float*)d_in[0];
    const float* gt    = (const float*)d_in[1];
    float* out = (float*)d_out;

    const int N = in_sizes[1] / (P_PERSONS * K_KPS * 2);

    group_loss_fused<<<N / GROUPS_PER_CTA, 32 * GROUPS_PER_CTA>>>(preds, gt, out, N);
}

// round 12
// speedup vs baseline: 1.0537x; 1.0537x over previous
#include <cuda_runtime.h>
#include <cuda_bf16.h>

// preds: [16,8,17,128,128] f32 -> N=128 groups, K=17, H=W=128
// gt:    [16,8,10,17,2]    f32 -> N=128, P=10, K=17, (x,y)
// FEAT_STRIDE = 4.0; out: [2] f32 = (within, across)

#define P_PERSONS 10
#define K_KPS     17
#define HMAP      128
#define WMAP      128
#define KP_HALF   9     // keypoints per lane (h=0: k0..8, h=1: k9..16 +1 masked)

// Single packed accumulator:
//   bits[36:64) : sum of per-group within  (fixed-point, scale 2^18)
//   bits[ 8:36) : sum of per-group across  (fixed-point, scale 2^20)
//   bits[ 0: 8) : arrival count (N=128 < 256)
// Fields are non-negative and bounded -> no cross-field carry. Integer adds
// are associative -> bit-deterministic across graph replays. Zero-init at
// module load; the last CTA resets it to 0.
__device__ unsigned long long g_acc;

#define QS        262144.0f            // 2^18 (lane-level quantization)
#define QS_INV    3.814697265625e-6f   // 2^-18
#define W_SCALE   262144.0f            // 2^18
#define A_SCALE   1048576.0f           // 2^20
#define W_INV     3.814697265625e-6f   // 2^-18
#define A_INV     9.5367431640625e-7f  // 2^-20

__global__ __launch_bounds__(32, 16)
void group_loss_fused(const float* __restrict__ preds,
                      const float* __restrict__ gt,
                      float* __restrict__ out,
                      int N)
{
    const int n    = blockIdx.x;
    const int lane = threadIdx.x;          // one warp per group
    const int p    = lane >> 1;            // person id (lanes 0..19)
    const int h    = lane & 1;             // half: 0 -> k0..8, 1 -> k9..16
    const bool active = (lane < 2 * P_PERSONS);

    float a0 = 0.0f, a1 = 0.0f, a2 = 0.0f;

    if (active) {
        const float2* gp = reinterpret_cast<const float2*>(gt)
                         + (n * P_PERSONS + p) * K_KPS;
        const float* pbase = preds + (size_t)n * K_KPS * (HMAP * WMAP);
        const int k0 = h ? 9 : 0;

        // Wave 1: 9 gt coords in flight at once (one overlapped latency).
        float2 gxy[KP_HALF];
        #pragma unroll
        for (int k = 0; k < KP_HALF; k++) {
            const int kk = min(k0 + k, K_KPS - 1);     // clamp keeps load in-bounds
            gxy[k] = __ldg(gp + kk);
        }

        int   off[KP_HALF];
        float msk[KP_HALF];
        #pragma unroll
        for (int k = 0; k < KP_HALF; k++) {
            const int kk = min(k0 + k, K_KPS - 1);
            // jnp.round == round-half-to-even == rintf (RN mode)
            const int x = (int)rintf(gxy[k].x * 0.25f);
            const int y = (int)rintf(gxy[k].y * 0.25f);
            bool v = (x >= 0) & (x < WMAP) & (y >= 0) & (y < HMAP);
            if (k0 + k > K_KPS - 1) v = false;          // mask the duplicate kp
            const int xc = min(max(x, 0), WMAP - 1);
            const int yc = min(max(y, 0), HMAP - 1);
            off[k] = kk * (HMAP * WMAP) + yc * WMAP + xc;
            msk[k] = v ? 1.0f : 0.0f;
        }

        // Wave 2: 9 gathers in flight at once (second overlapped latency).
        float val[KP_HALF];
        #pragma unroll
        for (int k = 0; k < KP_HALF; k++)
            val[k] = __ldg(pbase + off[k]);

        #pragma unroll
        for (int k = 0; k < KP_HALF; k++) {
            const float vm = val[k] * msk[k];
            a0 += vm;
            a1 += vm * val[k];
            a2 += msk[k];
        }
    }

    // Merge the two half-person partials (both lanes of the pair get sums).
    a0 += __shfl_xor_sync(0xFFFFFFFFu, a0, 1);
    a1 += __shfl_xor_sync(0xFFFFFFFFu, a1, 1);
    a2 += __shfl_xor_sync(0xFFFFFFFFu, a2, 1);

    const float safe = fmaxf(a2, 1.0f);
    const float inv  = __fdividef(1.0f, safe);
    const float e    = a0 * inv;                       // person embed (0 if cnt==0)
    const float pv   = (a2 > 0.0f) ? 1.0f : 0.0f;
    // within = E[v^2] - e^2 (exactly 0 when cnt==0; clamp fp32 cancellation)
    const float within_p = fmaxf(a1 * inv - e * e, 0.0f);

    // Hinge rows on even active lanes; embeds broadcast from even lanes.
    float hs = 0.0f;
    #pragma unroll
    for (int j = 0; j < P_PERSONS; j++) {
        const float ej  = __shfl_sync(0xFFFFFFFFu, e,  j << 1);
        const float pvj = __shfl_sync(0xFFFFFFFFu, pv, j << 1);
        if (j != p)
            hs += fmaxf(1.0f - fabsf(ej - e), 0.0f) * (pv * pvj);
    }
    const bool rowlane = active && (h == 0);

    // Single-instruction warp reductions on quantized values (deterministic).
    const unsigned wq  = rowlane ? __float2uint_rn(within_p * QS) : 0u;
    const unsigned hq  = rowlane ? __float2uint_rn(hs * QS)       : 0u;
    const unsigned vq  = (rowlane && pv > 0.0f) ? 1u : 0u;
    const unsigned wqt = __reduce_add_sync(0xFFFFFFFFu, wq);
    const unsigned hqt = __reduce_add_sync(0xFFFFFFFFu, hq);
    const unsigned vct = __reduce_add_sync(0xFFFFFFFFu, vq);

    if (lane == 0) {
        const float vcnt   = (float)vct;
        const float ps     = vcnt * vcnt - vcnt;        // off-diagonal valid pairs
        const float part_w = (float)wqt * QS_INV * (1.0f / (float)P_PERSONS);
        const float part_a = (ps > 0.0f)
                           ? __fdividef((float)hqt * QS_INV, ps) : 0.0f;

        const unsigned long long wfx = (unsigned long long)__float2uint_rn(part_w * W_SCALE);
        const unsigned long long afx = (unsigned long long)__float2uint_rn(part_a * A_SCALE);
        const unsigned long long packed = (wfx << 36) | (afx << 8) | 1ULL;

        // Single atomic: accumulates AND detects the last arriver.
        unsigned long long old;
        asm volatile("atom.relaxed.gpu.global.add.u64 %0, [%1], %2;"
                     : "=l"(old) : "l"(&g_acc), "l"(packed) : "memory");

        if ((old & 0xFFULL) == (unsigned long long)(N - 1)) {
            const unsigned long long tot = old + packed;
            // Reset for next graph replay (same-address coherence orders
            // this after every CTA's add, all of which precede ours).
            asm volatile("st.relaxed.gpu.global.u64 [%0], %1;"
                         :: "l"(&g_acc), "l"(0ULL) : "memory");
            const float inv_n = 1.0f / (float)N;
            const float wt = (float)(unsigned int)(tot >> 36);
            const float at = (float)(unsigned int)((tot >> 8) & 0xFFFFFFFULL);
            float2 res;
            res.x = wt * W_INV * inv_n;
            res.y = at * A_INV * inv_n;
            *reinterpret_cast<float2*>(out) = res;
        }
    }
}

extern "C" void kernel_launch(void* const* d_in, const int* in_sizes, int n_in,
                              void* d_out, int out_size)
{
    const float* preds = (const float*)d_in[0];
    const float* gt    = (const float*)d_in[1];
    float* out = (float*)d_out;

    const int N = in_sizes[1] / (P_PERSONS * K_KPS * 2);

    group_loss_fused<<<N, 32>>>(preds, gt, out, N);
}